// round 3
// baseline (speedup 1.0000x reference)
#include <cuda_runtime.h>
#include <math.h>

#define T      4096
#define P      8
#define DM     256
#define DF     4096
#define DK     1024
#define NE     9

// ---------------- scratch (device globals; no allocations allowed) ----------
__device__ float g_xlast[DF];
__device__ float g_q[DK];
__device__ float g_u[DF];
__device__ float g_utab[144];   // ou[72] | du[72]
__device__ float g_scores[T];
__device__ float g_att[T];
__device__ float g_wtab[144];   // wo[72] | wd[72]
__device__ float g_pc[DF];
__device__ float g_c[DF];
__device__ float g_ov[DK];
__device__ float g_oacc[DK];
__device__ int   g_io[T * P];
__device__ int   g_id[T * P];

#define LN1E4_OVER_2048 (9.210340371976184 / 2048.0)

// ---------------- K0: zero atomic accumulators ------------------------------
__global__ void k_zero() {
    int i = blockIdx.x * blockDim.x + threadIdx.x;   // 4096 threads
    if (i < DK) { g_q[i] = 0.f; g_ov[i] = 0.f; g_oacc[i] = 0.f; }
    if (i < DF) g_pc[i] = 0.f;
    if (i < 144) g_wtab[i] = 0.f;
}

// ---------------- K1: one-hot -> index extraction ---------------------------
__global__ void k_idx(const int* __restrict__ obs) {
    int i = blockIdx.x * blockDim.x + threadIdx.x;   // 0..32767 (t*P+p)
    const int* r0 = obs + (size_t)(2 * i) * NE;
    int io = 0, id = 0;
#pragma unroll
    for (int e = 0; e < NE; e++) {
        if (r0[e])      io = e;
        if (r0[NE + e]) id = e;
    }
    g_io[i] = io;
    g_id[i] = id;
}

// ---------------- K2: build x[T-1] (emb*16 + PE row) ------------------------
__global__ void k_xlast(const int* __restrict__ obs,
                        const float* __restrict__ oe,
                        const float* __restrict__ de) {
    int d = blockIdx.x * blockDim.x + threadIdx.x;   // 0..4095
    int p = d >> 9, r = d & 511;
    int row = 2 * ((T - 1) * P + p) + (r >= DM ? 1 : 0);
    const int* ro = obs + (size_t)row * NE;
    int idx = 0;
#pragma unroll
    for (int e = 0; e < NE; e++) if (ro[e]) idx = e;
    float ev = (r < DM) ? oe[idx * DM + r] : de[idx * DM + (r - DM)];
    int j = d >> 1;
    float fij = (float)exp(-(double)j * LN1E4_OVER_2048);
    float arg = (float)(T - 1) * fij;
    float s, c;
    sincosf(arg, &s, &c);
    g_xlast[d] = 16.0f * ev + ((d & 1) ? c : s);
}

// ---------------- column matvec: y[k] += sum_d x[d]*W[d,k] (atomic) ---------
// blockDim.x == K/4 (=256), gridDim.y splits D.
__global__ void k_colmv(const float* __restrict__ W, const float* __restrict__ x,
                        float* __restrict__ y, int K4, int dPerBlock) {
    int k4 = threadIdx.x;
    int d0 = blockIdx.y * dPerBlock;
    const float4* W4 = (const float4*)W;
    float4 acc = make_float4(0.f, 0.f, 0.f, 0.f);
#pragma unroll 8
    for (int i = 0; i < dPerBlock; i++) {
        int d = d0 + i;
        float xv = __ldg(&x[d]);
        float4 w = __ldg(&W4[(size_t)d * K4 + k4]);
        acc.x = fmaf(xv, w.x, acc.x);
        acc.y = fmaf(xv, w.y, acc.y);
        acc.z = fmaf(xv, w.z, acc.z);
        acc.w = fmaf(xv, w.w, acc.w);
    }
    atomicAdd(&y[4 * k4 + 0], acc.x);
    atomicAdd(&y[4 * k4 + 1], acc.y);
    atomicAdd(&y[4 * k4 + 2], acc.z);
    atomicAdd(&y[4 * k4 + 3], acc.w);
}

// ---------------- row matvec: y[row] = dot(W[row,:], x), warp per row -------
__global__ void k_rowmv(const float* __restrict__ W, const float* __restrict__ x,
                        float* __restrict__ y, int K) {
    int gw = (blockIdx.x * blockDim.x + threadIdx.x) >> 5;
    int lane = threadIdx.x & 31;
    const float4* Wr = (const float4*)(W + (size_t)gw * K);
    const float4* x4 = (const float4*)x;
    float acc = 0.f;
    int n4 = K >> 2;
#pragma unroll 4
    for (int i = lane; i < n4; i += 32) {
        float4 w = __ldg(&Wr[i]);
        float4 v = __ldg(&x4[i]);
        acc += w.x * v.x + w.y * v.y + w.z * v.z + w.w * v.w;
    }
    for (int o = 16; o; o >>= 1) acc += __shfl_xor_sync(0xffffffffu, acc, o);
    if (!lane) y[gw] = acc;
}

// ---------------- K5: embedding-dot tables ou/du (vs u) ---------------------
__global__ void k_utab(const float* __restrict__ oe, const float* __restrict__ de) {
    int gw = (blockIdx.x * blockDim.x + threadIdx.x) >> 5;   // 0..143
    int lane = threadIdx.x & 31;
    if (gw >= 144) return;
    int kind = gw / 72;
    int p = (gw % 72) / 9;
    int e = gw % 9;
    const float* emb = kind ? de : oe;
    const float* us = g_u + p * 512 + kind * DM;
    float acc = 0.f;
#pragma unroll 4
    for (int i = lane; i < DM; i += 32) acc += emb[e * DM + i] * us[i];
    for (int o = 16; o; o >>= 1) acc += __shfl_xor_sync(0xffffffffu, acc, o);
    if (!lane) g_utab[gw] = acc;
}

// ---------------- K6: scores_t = 16*table + PE_t . u  (rotation recurrence) -
__global__ void k_scores() {
    __shared__ float sh_peu[32];
    __shared__ float sh_tab[144];
    int tid = threadIdx.x;                // 256 threads
    if (tid < 144) sh_tab[tid] = g_utab[tid];
    if (tid < 32) sh_peu[tid] = 0.f;
    __syncthreads();
    int t0 = blockIdx.x * 32;             // 128 blocks
    float s[8], c[8], s1[8], c1[8], us[8], uc[8];
#pragma unroll
    for (int jj = 0; jj < 8; jj++) {
        int j = tid * 8 + jj;             // 0..2047
        float fij = (float)exp(-(double)j * LN1E4_OVER_2048);
        sincosf((float)t0 * fij, &s[jj], &c[jj]);
        sincosf(fij, &s1[jj], &c1[jj]);
        us[jj] = g_u[2 * j];
        uc[jj] = g_u[2 * j + 1];
    }
    for (int n = 0; n < 32; n++) {
        float part = 0.f;
#pragma unroll
        for (int jj = 0; jj < 8; jj++) part += us[jj] * s[jj] + uc[jj] * c[jj];
        for (int o = 16; o; o >>= 1) part += __shfl_xor_sync(0xffffffffu, part, o);
        if ((tid & 31) == 0) atomicAdd(&sh_peu[n], part);
#pragma unroll
        for (int jj = 0; jj < 8; jj++) {
            float ns = s[jj] * c1[jj] + c[jj] * s1[jj];
            float nc = c[jj] * c1[jj] - s[jj] * s1[jj];
            s[jj] = ns; c[jj] = nc;
        }
    }
    __syncthreads();
    if (tid < 32) {
        int t = t0 + tid;
        float es = 0.f;
#pragma unroll
        for (int p = 0; p < P; p++)
            es += sh_tab[p * 9 + g_io[t * P + p]] + sh_tab[72 + p * 9 + g_id[t * P + p]];
        g_scores[t] = 16.0f * es + sh_peu[tid];
    }
}

// ---------------- K7: softmax over 4096 scores (scale 1/32) -----------------
__global__ void k_softmax() {
    __shared__ float red[32];
    __shared__ float bc[2];
    int tid = threadIdx.x;               // 1024 threads
    float v[4];
    float m = -1e30f;
#pragma unroll
    for (int i = 0; i < 4; i++) {
        v[i] = g_scores[tid + 1024 * i] * (1.0f / 32.0f);
        m = fmaxf(m, v[i]);
    }
    for (int o = 16; o; o >>= 1) m = fmaxf(m, __shfl_xor_sync(0xffffffffu, m, o));
    if ((tid & 31) == 0) red[tid >> 5] = m;
    __syncthreads();
    if (tid < 32) {
        float x = red[tid];
        for (int o = 16; o; o >>= 1) x = fmaxf(x, __shfl_xor_sync(0xffffffffu, x, o));
        if (tid == 0) bc[0] = x;
    }
    __syncthreads();
    m = bc[0];
    float sum = 0.f;
#pragma unroll
    for (int i = 0; i < 4; i++) { v[i] = expf(v[i] - m); sum += v[i]; }
    for (int o = 16; o; o >>= 1) sum += __shfl_xor_sync(0xffffffffu, sum, o);
    if ((tid & 31) == 0) red[tid >> 5] = sum;
    __syncthreads();
    if (tid < 32) {
        float x = red[tid];
        for (int o = 16; o; o >>= 1) x += __shfl_xor_sync(0xffffffffu, x, o);
        if (tid == 0) bc[1] = x;
    }
    __syncthreads();
    float inv = 1.0f / bc[1];
#pragma unroll
    for (int i = 0; i < 4; i++) g_att[tid + 1024 * i] = v[i] * inv;
}

// ---------------- K8a: pc = sum_t att_t * PE_t (rotation recurrence) --------
__global__ void k_pc() {
    int g = blockIdx.x * blockDim.x + threadIdx.x;  // 0..32767
    int j = g & 2047, ch = g >> 11;
    int t0 = ch << 8;
    float fij = (float)exp(-(double)j * LN1E4_OVER_2048);
    float s, c, s1, c1;
    sincosf((float)t0 * fij, &s, &c);
    sincosf(fij, &s1, &c1);
    float as = 0.f, ac = 0.f;
    for (int n = 0; n < 256; n++) {
        float w = __ldg(&g_att[t0 + n]);
        as = fmaf(w, s, as);
        ac = fmaf(w, c, ac);
        float ns = s * c1 + c * s1;
        float nc = c * c1 - s * s1;
        s = ns; c = nc;
    }
    atomicAdd(&g_pc[2 * j], as);
    atomicAdd(&g_pc[2 * j + 1], ac);
}

// ---------------- K8b: weight tables wo/wd (att scatter) --------------------
__global__ void k_wtab() {
    __shared__ float sh[144];
    int tid = threadIdx.x;
    if (tid < 144) sh[tid] = 0.f;
    __syncthreads();
    int pair = blockIdx.x * blockDim.x + tid;       // 0..32767
    int t = pair >> 3, p = pair & 7;
    float w = g_att[t];
    atomicAdd(&sh[p * 9 + g_io[t * P + p]], w);
    atomicAdd(&sh[72 + p * 9 + g_id[t * P + p]], w);
    __syncthreads();
    if (tid < 144) atomicAdd(&g_wtab[tid], sh[tid]);
}

// ---------------- K9: c[d] = 16*sum_e w[p][e]*emb[e,r] + pc[d] --------------
__global__ void k_cbuild(const float* __restrict__ oe, const float* __restrict__ de) {
    int d = blockIdx.x * blockDim.x + threadIdx.x;  // 0..4095
    int p = d >> 9, r = d & 511;
    float acc = 0.f;
    if (r < DM) {
#pragma unroll
        for (int e = 0; e < NE; e++) acc += g_wtab[p * 9 + e] * __ldg(&oe[e * DM + r]);
    } else {
        int rr = r - DM;
#pragma unroll
        for (int e = 0; e < NE; e++) acc += g_wtab[72 + p * 9 + e] * __ldg(&de[e * DM + rr]);
    }
    g_c[d] = 16.0f * acc + g_pc[d];
}

// ---------------- K12: relu + policy/value heads ----------------------------
__global__ void k_logits(const float* __restrict__ Wo, const float* __restrict__ bo,
                         const float* __restrict__ Wd, const float* __restrict__ bd,
                         const float* __restrict__ Wv, const float* __restrict__ bv,
                         float* __restrict__ out, int out_size) {
    int o = blockIdx.x;                  // 129 blocks
    const float* Wr;
    float bias;
    if (o < 64)       { Wr = Wo + o * DK;        bias = bo[o]; }
    else if (o < 128) { Wr = Wd + (o - 64) * DK; bias = bd[o - 64]; }
    else              { Wr = Wv;                 bias = bv[0]; }
    int tid = threadIdx.x;               // 128 threads
    float acc = 0.f;
#pragma unroll 4
    for (int i = tid; i < DK; i += 128)
        acc += fmaxf(g_oacc[i], 0.f) * __ldg(&Wr[i]);
    for (int off = 16; off; off >>= 1) acc += __shfl_xor_sync(0xffffffffu, acc, off);
    __shared__ float sred[4];
    if ((tid & 31) == 0) sred[tid >> 5] = acc;
    __syncthreads();
    if (tid == 0 && o < out_size)
        out[o] = sred[0] + sred[1] + sred[2] + sred[3] + bias;
}

// ---------------- host launcher ---------------------------------------------
extern "C" void kernel_launch(void* const* d_in, const int* in_sizes, int n_in,
                              void* d_out, int out_size) {
    const int*   obs = (const int*)d_in[0];
    const float* oe  = (const float*)d_in[1];
    const float* de  = (const float*)d_in[2];
    const float* WQ  = (const float*)d_in[3];
    const float* WK  = (const float*)d_in[4];
    const float* WV  = (const float*)d_in[5];
    const float* WO  = (const float*)d_in[6];
    const float* Wo  = (const float*)d_in[7];
    const float* bo  = (const float*)d_in[8];
    const float* Wd  = (const float*)d_in[9];
    const float* bd  = (const float*)d_in[10];
    const float* Wv  = (const float*)d_in[11];
    const float* bv  = (const float*)d_in[12];
    float* out = (float*)d_out;

    float *p_xlast, *p_q, *p_u, *p_c, *p_ov, *p_oacc;
    cudaGetSymbolAddress((void**)&p_xlast, g_xlast);
    cudaGetSymbolAddress((void**)&p_q, g_q);
    cudaGetSymbolAddress((void**)&p_u, g_u);
    cudaGetSymbolAddress((void**)&p_c, g_c);
    cudaGetSymbolAddress((void**)&p_ov, g_ov);
    cudaGetSymbolAddress((void**)&p_oacc, g_oacc);

    k_zero<<<16, 256>>>();
    k_idx<<<128, 256>>>(obs);
    k_xlast<<<16, 256>>>(obs, oe, de);
    // q = xlast @ WQ   (D=4096, K=1024)
    k_colmv<<<dim3(1, 128), 256>>>(WQ, p_xlast, p_q, DK / 4, 32);
    // u = WK @ q       (4096 rows of length 1024)
    k_rowmv<<<512, 256>>>(WK, p_q, p_u, DK);
    k_utab<<<18, 256>>>(oe, de);
    k_scores<<<128, 256>>>();
    k_softmax<<<1, 1024>>>();
    k_pc<<<128, 256>>>();
    k_wtab<<<128, 256>>>();
    k_cbuild<<<16, 256>>>(oe, de);
    // ov = c @ WV      (D=4096, K=1024)
    k_colmv<<<dim3(1, 128), 256>>>(WV, p_c, p_ov, DK / 4, 32);
    // o_last = ov @ WO (D=1024, K=1024)
    k_colmv<<<dim3(1, 64), 256>>>(WO, p_ov, p_oacc, DK / 4, 16);
    k_logits<<<129, 128>>>(Wo, bo, Wd, bd, Wv, bv, out, out_size);
}